// round 1
// baseline (speedup 1.0000x reference)
#include <cuda_runtime.h>
#include <math.h>

// Problem constants
#define BB 4
#define SS 1024
#define EE 1024
#define HH 16
#define DKK 64
#define PER (BB * HH * SS * DKK)       // 4194304 elems per q/k/v tensor
#define NEGV (-10000.0f)

// Scratch (allocation-free rule: __device__ globals)
__device__ float g_qkv[3 * BB * HH * SS * DKK];   // q|k|v, each [B,H,S,DK]
__device__ float g_ctx[BB * SS * EE];             // [B,S,E] attention context

// ---------------------------------------------------------------------------
// QKV GEMM: out(4096,3072) = x(4096,1024) @ qkv_w(3072,1024)^T + qkv_b
// Epilogue: zero padded rows (incl. bias), scatter to [which][B,H,S,DK].
// ---------------------------------------------------------------------------
__global__ __launch_bounds__(256) void qkv_gemm_kernel(
    const float* __restrict__ x, const float* __restrict__ w,
    const float* __restrict__ bias, const unsigned int* __restrict__ kpm)
{
    __shared__ float As[16][64];
    __shared__ float Bs[16][64];
    const int tid = threadIdx.x;
    const int tx = tid & 15, ty = tid >> 4;
    const int m0 = blockIdx.y * 64, n0 = blockIdx.x * 64;
    const int lr = tid >> 2;          // 0..63 load row
    const int lc = (tid & 3) * 4;     // 0,4,8,12 load col

    float acc[4][4];
#pragma unroll
    for (int i = 0; i < 4; i++)
#pragma unroll
        for (int j = 0; j < 4; j++) acc[i][j] = 0.0f;

    for (int k0 = 0; k0 < 1024; k0 += 16) {
        float4 a = *(const float4*)(x + (size_t)(m0 + lr) * 1024 + k0 + lc);
        float4 bv = *(const float4*)(w + (size_t)(n0 + lr) * 1024 + k0 + lc);
        __syncthreads();
        As[lc + 0][lr] = a.x;  As[lc + 1][lr] = a.y;
        As[lc + 2][lr] = a.z;  As[lc + 3][lr] = a.w;
        Bs[lc + 0][lr] = bv.x; Bs[lc + 1][lr] = bv.y;
        Bs[lc + 2][lr] = bv.z; Bs[lc + 3][lr] = bv.w;
        __syncthreads();
#pragma unroll
        for (int kk = 0; kk < 16; kk++) {
            float4 ra = *(const float4*)&As[kk][ty * 4];
            float4 rb = *(const float4*)&Bs[kk][tx * 4];
            float fa[4] = {ra.x, ra.y, ra.z, ra.w};
            float fb[4] = {rb.x, rb.y, rb.z, rb.w};
#pragma unroll
            for (int i = 0; i < 4; i++)
#pragma unroll
                for (int j = 0; j < 4; j++) acc[i][j] += fa[i] * fb[j];
        }
    }

#pragma unroll
    for (int i = 0; i < 4; i++) {
        const int r = m0 + ty * 4 + i;
        const int b = r >> 10, s = r & 1023;
        const bool pad = (kpm[b * 1024 + s] != 0u);
#pragma unroll
        for (int j = 0; j < 4; j++) {
            const int c = n0 + tx * 4 + j;
            const float v = pad ? 0.0f : (acc[i][j] + bias[c]);
            const int which = c >> 10;
            const int e = c & 1023;
            const int h = e >> 6, d = e & 63;
            g_qkv[which * PER + (((b * HH + h) * SS + s) * DKK) + d] = v;
        }
    }
}

// ---------------------------------------------------------------------------
// Attention: per block = one (b, h, 16 query rows). Exact softmax, writes
// normalized weights to gmem and context to g_ctx.
// smem: scores[16][1024] | Qs[16*64] | KVs[64][65] | rowl[16]
// ---------------------------------------------------------------------------
#define TQ 16
#define TK 64
#define KVP 65

__global__ __launch_bounds__(256) void attn_kernel(
    const float* __restrict__ attn_mask, const unsigned int* __restrict__ kpm,
    float* __restrict__ wout)
{
    extern __shared__ float smem[];
    float* scores = smem;                       // TQ * SS
    float* Qs     = scores + TQ * SS;           // TQ * DKK
    float* KVs    = Qs + TQ * DKK;              // TK * KVP
    float* rowl   = KVs + TK * KVP;             // TQ

    const int b = blockIdx.z, h = blockIdx.y, q0 = blockIdx.x * TQ;
    const int tid = threadIdx.x;

    const float* Qg = g_qkv + (((size_t)(b * HH + h) * SS) + q0) * DKK;
    const float* Kg = g_qkv + PER     + ((size_t)(b * HH + h) * SS) * DKK;
    const float* Vg = g_qkv + 2 * PER + ((size_t)(b * HH + h) * SS) * DKK;

    // Load Q tile (contiguous 1024 floats)
    for (int i = tid; i < TQ * DKK; i += 256) Qs[i] = Qg[i];

    const int kc  = tid & 63;   // k column within tile
    const int qg0 = tid >> 6;   // 0..3 -> handles q = qg0 + 4u

    // ---- Phase A: scores = dot/8 + causal mask; replace with NEG if key padded
    for (int k0 = 0; k0 < SS; k0 += TK) {
        __syncthreads();
        for (int i = tid; i < (TK * DKK) / 4; i += 256) {
            const int base = i * 4;
            const int row = base >> 6, col = base & 63;
            float4 v = *(const float4*)(Kg + (size_t)(k0 + row) * DKK + col);
            KVs[row * KVP + col + 0] = v.x; KVs[row * KVP + col + 1] = v.y;
            KVs[row * KVP + col + 2] = v.z; KVs[row * KVP + col + 3] = v.w;
        }
        __syncthreads();

        const int kglob = k0 + kc;
        const bool kpad = (kpm[b * 1024 + kglob] != 0u);
        float dotv[4] = {0.f, 0.f, 0.f, 0.f};
#pragma unroll 8
        for (int d = 0; d < DKK; d++) {
            const float kv = KVs[kc * KVP + d];
#pragma unroll
            for (int u = 0; u < 4; u++)
                dotv[u] += Qs[(qg0 + 4 * u) * DKK + d] * kv;
        }
#pragma unroll
        for (int u = 0; u < 4; u++) {
            const int q = qg0 + 4 * u;
            float sval = dotv[u] * 0.125f + attn_mask[(size_t)(q0 + q) * SS + kglob];
            if (kpad) sval = NEGV;   // replace semantics (jnp.where)
            scores[q * SS + kglob] = sval;
        }
    }
    __syncthreads();

    // ---- Phase B: rowwise max, exp, sum (8 warps x 2 rows)
    {
        const int warp = tid >> 5, lane = tid & 31;
        for (int r = warp; r < TQ; r += 8) {
            float m = -1e30f;
            for (int j = lane; j < SS; j += 32) m = fmaxf(m, scores[r * SS + j]);
#pragma unroll
            for (int off = 16; off; off >>= 1)
                m = fmaxf(m, __shfl_xor_sync(0xFFFFFFFFu, m, off));
            float l = 0.0f;
            for (int j = lane; j < SS; j += 32) {
                const float e = __expf(scores[r * SS + j] - m);
                scores[r * SS + j] = e;
                l += e;
            }
#pragma unroll
            for (int off = 16; off; off >>= 1)
                l += __shfl_xor_sync(0xFFFFFFFFu, l, off);
            if (lane == 0) rowl[r] = 1.0f / l;
        }
    }
    __syncthreads();

    // ---- Phase C: normalize, write attn_weights to gmem, keep normalized in smem
    {
        const size_t wbase = (((size_t)(b * HH + h) * SS) + q0) * SS;
        for (int idx = tid; idx < TQ * SS; idx += 256) {
            const int q = idx >> 10, j = idx & 1023;
            const float wv = scores[idx] * rowl[q];
            scores[idx] = wv;
            wout[wbase + (size_t)q * SS + j] = wv;
        }
    }

    // ---- Phase D: context = W @ V, accumulate 4 outputs per thread
    {
        const int d = tid & 63;     // output dim
        float acc[4] = {0.f, 0.f, 0.f, 0.f};
        for (int k0 = 0; k0 < SS; k0 += TK) {
            __syncthreads();
            for (int i = tid; i < (TK * DKK) / 4; i += 256) {
                const int base = i * 4;
                const int row = base >> 6, col = base & 63;
                float4 v = *(const float4*)(Vg + (size_t)(k0 + row) * DKK + col);
                KVs[row * KVP + col + 0] = v.x; KVs[row * KVP + col + 1] = v.y;
                KVs[row * KVP + col + 2] = v.z; KVs[row * KVP + col + 3] = v.w;
            }
            __syncthreads();
#pragma unroll 8
            for (int kj = 0; kj < TK; kj++) {
                const float vv = KVs[kj * KVP + d];
#pragma unroll
                for (int u = 0; u < 4; u++)
                    acc[u] += scores[(qg0 + 4 * u) * SS + k0 + kj] * vv;
            }
        }
#pragma unroll
        for (int u = 0; u < 4; u++) {
            const int q = qg0 + 4 * u;
            g_ctx[((size_t)(b * SS + q0 + q)) * EE + h * DKK + d] = acc[u];
        }
    }
}

// ---------------------------------------------------------------------------
// Output projection: out(4096,1024) = ctx(4096,1024) @ out_w(1024,1024)^T + out_b
// ---------------------------------------------------------------------------
__global__ __launch_bounds__(256) void out_gemm_kernel(
    const float* __restrict__ w, const float* __restrict__ bias,
    float* __restrict__ out)
{
    __shared__ float As[16][64];
    __shared__ float Bs[16][64];
    const int tid = threadIdx.x;
    const int tx = tid & 15, ty = tid >> 4;
    const int m0 = blockIdx.y * 64, n0 = blockIdx.x * 64;
    const int lr = tid >> 2;
    const int lc = (tid & 3) * 4;

    float acc[4][4];
#pragma unroll
    for (int i = 0; i < 4; i++)
#pragma unroll
        for (int j = 0; j < 4; j++) acc[i][j] = 0.0f;

    for (int k0 = 0; k0 < 1024; k0 += 16) {
        float4 a = *(const float4*)(g_ctx + (size_t)(m0 + lr) * 1024 + k0 + lc);
        float4 bv = *(const float4*)(w + (size_t)(n0 + lr) * 1024 + k0 + lc);
        __syncthreads();
        As[lc + 0][lr] = a.x;  As[lc + 1][lr] = a.y;
        As[lc + 2][lr] = a.z;  As[lc + 3][lr] = a.w;
        Bs[lc + 0][lr] = bv.x; Bs[lc + 1][lr] = bv.y;
        Bs[lc + 2][lr] = bv.z; Bs[lc + 3][lr] = bv.w;
        __syncthreads();
#pragma unroll
        for (int kk = 0; kk < 16; kk++) {
            float4 ra = *(const float4*)&As[kk][ty * 4];
            float4 rb = *(const float4*)&Bs[kk][tx * 4];
            float fa[4] = {ra.x, ra.y, ra.z, ra.w};
            float fb[4] = {rb.x, rb.y, rb.z, rb.w};
#pragma unroll
            for (int i = 0; i < 4; i++)
#pragma unroll
                for (int j = 0; j < 4; j++) acc[i][j] += fa[i] * fb[j];
        }
    }

#pragma unroll
    for (int i = 0; i < 4; i++) {
        const int r = m0 + ty * 4 + i;
#pragma unroll
        for (int j = 0; j < 4; j++) {
            const int c = n0 + tx * 4 + j;
            out[(size_t)r * 1024 + c] = acc[i][j] + bias[c];
        }
    }
}

// ---------------------------------------------------------------------------
extern "C" void kernel_launch(void* const* d_in, const int* in_sizes, int n_in,
                              void* d_out, int out_size)
{
    const float*        x         = (const float*)d_in[0];
    const float*        attn_mask = (const float*)d_in[1];
    const unsigned int* kpm       = (const unsigned int*)d_in[2];
    const float*        qkv_w     = (const float*)d_in[3];
    const float*        qkv_b     = (const float*)d_in[4];
    const float*        out_w     = (const float*)d_in[5];
    const float*        out_b     = (const float*)d_in[6];

    float* out  = (float*)d_out;
    float* wout = out + (size_t)BB * SS * EE;   // attn_weights region

    const int attn_smem = (TQ * SS + TQ * DKK + TK * KVP + TQ) * 4;  // ~86.5 KB
    cudaFuncSetAttribute(attn_kernel,
                         cudaFuncAttributeMaxDynamicSharedMemorySize, attn_smem);

    // 1) QKV projection -> g_qkv (padded rows zeroed)
    qkv_gemm_kernel<<<dim3(48, 64), 256>>>(x, qkv_w, qkv_b, kpm);

    // 2) Attention: weights -> d_out tail, context -> g_ctx
    attn_kernel<<<dim3(SS / TQ, HH, BB), 256, attn_smem>>>(attn_mask, kpm, wout);

    // 3) Output projection -> d_out head
    out_gemm_kernel<<<dim3(16, 64), 256>>>(out_w, out_b, out);
}

// round 3
// speedup vs baseline: 1.0195x; 1.0195x over previous
#include <cuda_runtime.h>
#include <math.h>

// Problem constants
#define BB 4
#define SS 1024
#define EE 1024
#define HH 16
#define DKK 64
#define PER (BB * HH * SS * DKK)
#define NEGV (-10000.0f)

// Scratch
__device__ float g_qkv[3 * BB * HH * SS * DKK];   // q|k|v, each [B,H,S,DK]
__device__ float g_ctx[BB * SS * EE];             // [B,S,E]

// ---------------------------------------------------------------------------
// 128x128x8 SGEMM, 256 threads, 8x8 per thread, double-buffered smem.
// QKV=true:  A = x (arg), scatter epilogue into g_qkv with padding zeroing.
// QKV=false: A = g_ctx (device symbol, resolved IN DEVICE CODE), plain epilogue.
// ---------------------------------------------------------------------------
template <bool QKV>
__global__ __launch_bounds__(256) void gemm128_kernel(
    const float* __restrict__ A_arg, const float* __restrict__ W,
    const float* __restrict__ bias, const unsigned int* __restrict__ kpm,
    float* __restrict__ out)
{
    __shared__ float As[2][8][128];
    __shared__ float Bs[2][8][128];

    const float* A = QKV ? A_arg : (const float*)g_ctx;  // device-side symbol ref

    const int tid = threadIdx.x;
    const int tx = tid & 15, ty = tid >> 4;
    const int m0 = blockIdx.y * 128, n0 = blockIdx.x * 128;

    const int lrow  = tid & 127;
    const int lcol4 = (tid >> 7) * 4;   // 0 or 4

    const float* Aptr = A + (size_t)(m0 + lrow) * 1024 + lcol4;
    const float* Wptr = W + (size_t)(n0 + lrow) * 1024 + lcol4;

    float acc[8][8];
#pragma unroll
    for (int i = 0; i < 8; i++)
#pragma unroll
        for (int j = 0; j < 8; j++) acc[i][j] = 0.0f;

    // Preload tile 0
    {
        float4 a = *(const float4*)Aptr;
        float4 b = *(const float4*)Wptr;
        As[0][lcol4 + 0][lrow] = a.x; As[0][lcol4 + 1][lrow] = a.y;
        As[0][lcol4 + 2][lrow] = a.z; As[0][lcol4 + 3][lrow] = a.w;
        Bs[0][lcol4 + 0][lrow] = b.x; Bs[0][lcol4 + 1][lrow] = b.y;
        Bs[0][lcol4 + 2][lrow] = b.z; Bs[0][lcol4 + 3][lrow] = b.w;
    }
    __syncthreads();

    for (int kt = 0; kt < 128; kt++) {
        const int cur = kt & 1;
        float4 an, bn;
        if (kt < 127) {
            an = *(const float4*)(Aptr + (kt + 1) * 8);
            bn = *(const float4*)(Wptr + (kt + 1) * 8);
        }
#pragma unroll
        for (int kk = 0; kk < 8; kk++) {
            float af[8], bf[8];
            *(float4*)&af[0] = *(const float4*)&As[cur][kk][ty * 8];
            *(float4*)&af[4] = *(const float4*)&As[cur][kk][ty * 8 + 4];
            *(float4*)&bf[0] = *(const float4*)&Bs[cur][kk][tx * 8];
            *(float4*)&bf[4] = *(const float4*)&Bs[cur][kk][tx * 8 + 4];
#pragma unroll
            for (int i = 0; i < 8; i++)
#pragma unroll
                for (int j = 0; j < 8; j++) acc[i][j] += af[i] * bf[j];
        }
        if (kt < 127) {
            const int nxt = cur ^ 1;
            As[nxt][lcol4 + 0][lrow] = an.x; As[nxt][lcol4 + 1][lrow] = an.y;
            As[nxt][lcol4 + 2][lrow] = an.z; As[nxt][lcol4 + 3][lrow] = an.w;
            Bs[nxt][lcol4 + 0][lrow] = bn.x; Bs[nxt][lcol4 + 1][lrow] = bn.y;
            Bs[nxt][lcol4 + 2][lrow] = bn.z; Bs[nxt][lcol4 + 3][lrow] = bn.w;
            __syncthreads();
        }
    }

    if (QKV) {
#pragma unroll
        for (int i = 0; i < 8; i++) {
            const int r = m0 + ty * 8 + i;
            const int b = r >> 10, s = r & 1023;
            const bool pad = (kpm[b * 1024 + s] != 0u);
#pragma unroll
            for (int j = 0; j < 8; j++) {
                const int c = n0 + tx * 8 + j;
                const float v = pad ? 0.0f : (acc[i][j] + bias[c]);
                const int which = c >> 10;
                const int e = c & 1023;
                const int h = e >> 6, d = e & 63;
                g_qkv[which * PER + (((b * HH + h) * SS + s) * DKK) + d] = v;
            }
        }
    } else {
#pragma unroll
        for (int i = 0; i < 8; i++) {
            const int r = m0 + ty * 8 + i;
#pragma unroll
            for (int j = 0; j < 8; j++) {
                const int c = n0 + tx * 8 + j;
                out[(size_t)r * 1024 + c] = acc[i][j] + bias[c];
            }
        }
    }
}

// ---------------------------------------------------------------------------
// Attention: per block = (b, h, 16 q rows). Exact softmax; writes normalized
// weights to gmem and context into g_ctx.
// smem: scores[16][1024] | Qs[16*64] | KVs[64*68] | rowl[16]
// ---------------------------------------------------------------------------
#define TQ 16
#define TK 64
#define KVP 68

__global__ __launch_bounds__(256) void attn_kernel(
    const float* __restrict__ attn_mask, const unsigned int* __restrict__ kpm,
    float* __restrict__ wout)
{
    extern __shared__ float smem[];
    float* scores = smem;                       // TQ * SS
    float* Qs     = scores + TQ * SS;           // TQ * DKK
    float* KVs    = Qs + TQ * DKK;              // TK * KVP
    float* rowl   = KVs + TK * KVP;             // TQ

    const int b = blockIdx.z, h = blockIdx.y, q0 = blockIdx.x * TQ;
    const int tid = threadIdx.x;

    const float* Qg = g_qkv + (((size_t)(b * HH + h) * SS) + q0) * DKK;
    const float* Kg = g_qkv + PER     + ((size_t)(b * HH + h) * SS) * DKK;
    const float* Vg = g_qkv + 2 * PER + ((size_t)(b * HH + h) * SS) * DKK;

    for (int i = tid; i < TQ * DKK; i += 256) Qs[i] = Qg[i];

    const int kc  = tid & 63;
    const int qg0 = tid >> 6;   // 0..3

    // ---- Phase A: scores = dot/8 + causal mask; NEG where key padded
    for (int k0 = 0; k0 < SS; k0 += TK) {
        __syncthreads();
        for (int i = tid; i < (TK * DKK) / 4; i += 256) {
            const int base = i * 4;
            const int row = base >> 6, col = base & 63;
            float4 v = *(const float4*)(Kg + (size_t)(k0 + row) * DKK + col);
            *(float4*)&KVs[row * KVP + col] = v;
        }
        __syncthreads();

        const int kglob = k0 + kc;
        const bool kpad = (kpm[b * 1024 + kglob] != 0u);
        float dotv[4] = {0.f, 0.f, 0.f, 0.f};
#pragma unroll
        for (int d = 0; d < DKK; d += 4) {
            float kv[4];
            *(float4*)kv = *(const float4*)&KVs[kc * KVP + d];
#pragma unroll
            for (int u = 0; u < 4; u++) {
                float qv[4];
                *(float4*)qv = *(const float4*)&Qs[(qg0 + 4 * u) * DKK + d];
                dotv[u] += qv[0] * kv[0] + qv[1] * kv[1]
                         + qv[2] * kv[2] + qv[3] * kv[3];
            }
        }
#pragma unroll
        for (int u = 0; u < 4; u++) {
            const int q = qg0 + 4 * u;
            float sval = dotv[u] * 0.125f + attn_mask[(size_t)(q0 + q) * SS + kglob];
            if (kpad) sval = NEGV;
            scores[q * SS + kglob] = sval;
        }
    }
    __syncthreads();

    // ---- Phase B: rowwise max, exp, sum
    {
        const int warp = tid >> 5, lane = tid & 31;
        for (int r = warp; r < TQ; r += 8) {
            float m = -1e30f;
            for (int j = lane; j < SS; j += 32) m = fmaxf(m, scores[r * SS + j]);
#pragma unroll
            for (int off = 16; off; off >>= 1)
                m = fmaxf(m, __shfl_xor_sync(0xFFFFFFFFu, m, off));
            float l = 0.0f;
            for (int j = lane; j < SS; j += 32) {
                const float e = __expf(scores[r * SS + j] - m);
                scores[r * SS + j] = e;
                l += e;
            }
#pragma unroll
            for (int off = 16; off; off >>= 1)
                l += __shfl_xor_sync(0xFFFFFFFFu, l, off);
            if (lane == 0) rowl[r] = 1.0f / l;
        }
    }
    __syncthreads();

    // ---- Phase C: normalize + write attn_weights (float4)
    {
        const size_t wbase = (((size_t)(b * HH + h) * SS) + q0) * SS;
        for (int idx = tid; idx < (TQ * SS) / 4; idx += 256) {
            const int base = idx * 4;
            const int q = base >> 10, j = base & 1023;
            float4 wv = *(const float4*)&scores[base];
            const float rl = rowl[q];
            wv.x *= rl; wv.y *= rl; wv.z *= rl; wv.w *= rl;
            *(float4*)&scores[base] = wv;
            *(float4*)&wout[wbase + (size_t)q * SS + j] = wv;
        }
    }

    // ---- Phase D: context = W @ V
    {
        const int d = kc;
        float acc[4] = {0.f, 0.f, 0.f, 0.f};
        for (int k0 = 0; k0 < SS; k0 += TK) {
            __syncthreads();
            for (int i = tid; i < (TK * DKK) / 4; i += 256) {
                const int base = i * 4;
                const int row = base >> 6, col = base & 63;
                float4 v = *(const float4*)(Vg + (size_t)(k0 + row) * DKK + col);
                *(float4*)&KVs[row * KVP + col] = v;
            }
            __syncthreads();
#pragma unroll
            for (int kj = 0; kj < TK; kj += 4) {
                float w0[4], w1[4], w2[4], w3[4];
                *(float4*)w0 = *(const float4*)&scores[(qg0 +  0) * SS + k0 + kj];
                *(float4*)w1 = *(const float4*)&scores[(qg0 +  4) * SS + k0 + kj];
                *(float4*)w2 = *(const float4*)&scores[(qg0 +  8) * SS + k0 + kj];
                *(float4*)w3 = *(const float4*)&scores[(qg0 + 12) * SS + k0 + kj];
#pragma unroll
                for (int j = 0; j < 4; j++) {
                    const float vv = KVs[(kj + j) * KVP + d];
                    acc[0] += w0[j] * vv;
                    acc[1] += w1[j] * vv;
                    acc[2] += w2[j] * vv;
                    acc[3] += w3[j] * vv;
                }
            }
        }
#pragma unroll
        for (int u = 0; u < 4; u++) {
            const int q = qg0 + 4 * u;
            g_ctx[((size_t)(b * SS + q0 + q)) * EE + h * DKK + d] = acc[u];
        }
    }
}

// ---------------------------------------------------------------------------
extern "C" void kernel_launch(void* const* d_in, const int* in_sizes, int n_in,
                              void* d_out, int out_size)
{
    const float*        x         = (const float*)d_in[0];
    const float*        attn_mask = (const float*)d_in[1];
    const unsigned int* kpm       = (const unsigned int*)d_in[2];
    const float*        qkv_w     = (const float*)d_in[3];
    const float*        qkv_b     = (const float*)d_in[4];
    const float*        out_w     = (const float*)d_in[5];
    const float*        out_b     = (const float*)d_in[6];

    float* out  = (float*)d_out;
    float* wout = out + (size_t)BB * SS * EE;

    const int attn_smem = (TQ * SS + TQ * DKK + TK * KVP + TQ) * 4;
    cudaFuncSetAttribute(attn_kernel,
                         cudaFuncAttributeMaxDynamicSharedMemorySize, attn_smem);

    // 1) QKV projection -> g_qkv (padded rows zeroed)
    gemm128_kernel<true><<<dim3(24, 32), 256>>>(x, qkv_w, qkv_b, kpm, nullptr);

    // 2) Attention: weights -> d_out tail, context -> g_ctx
    attn_kernel<<<dim3(SS / TQ, HH, BB), 256, attn_smem>>>(attn_mask, kpm, wout);

    // 3) Output projection (A = g_ctx resolved in device code) -> d_out head
    gemm128_kernel<false><<<dim3(8, 32), 256>>>(nullptr, out_w, out_b, nullptr, out);
}

// round 4
// speedup vs baseline: 1.3053x; 1.2804x over previous
#include <cuda_runtime.h>
#include <cuda_bf16.h>
#include <math.h>

// Problem constants
#define BB 4
#define SS 1024
#define EE 1024
#define HH 16
#define DKK 64
#define PER (BB * HH * SS * DKK)
#define NEGV (-10000.0f)

// Scratch
__device__ float g_qkv[3 * BB * HH * SS * DKK];   // q|k|v, each [B,H,S,DK]
__device__ float g_ctx[BB * SS * EE];             // [B,S,E]

// ---------------------------------------------------------------------------
// bf16 split-precision helpers
// ---------------------------------------------------------------------------
__device__ __forceinline__ void mma_bf16(float* d, const unsigned* a,
                                         unsigned b0, unsigned b1)
{
    asm("mma.sync.aligned.m16n8k16.row.col.f32.bf16.bf16.f32 "
        "{%0,%1,%2,%3}, {%4,%5,%6,%7}, {%8,%9}, {%0,%1,%2,%3};"
        : "+f"(d[0]), "+f"(d[1]), "+f"(d[2]), "+f"(d[3])
        : "r"(a[0]), "r"(a[1]), "r"(a[2]), "r"(a[3]), "r"(b0), "r"(b1));
}

// pack two floats' bf16-hi parts into one u32 (x -> low half, y -> high half)
__device__ __forceinline__ unsigned pack_hi(float x, float y,
                                            float& rx, float& ry)
{
    __nv_bfloat162 t = __floats2bfloat162_rn(x, y);
    rx = x - __bfloat162float(t.x);
    ry = y - __bfloat162float(t.y);
    unsigned u; *(__nv_bfloat162*)&u = t; return u;
}
__device__ __forceinline__ unsigned pack_lo(float rx, float ry)
{
    __nv_bfloat162 t = __floats2bfloat162_rn(rx, ry);
    unsigned u; *(__nv_bfloat162*)&u = t; return u;
}

// ---------------------------------------------------------------------------
// Tensor-core GEMM: C(M,N) = A(M,1024) @ W(N,1024)^T + bias
// bf16 split (hi+lo): acc += Ah*Wh + Ah*Wl + Al*Wh  (error ~2^-16, safe)
// 128x128 block tile, 8 warps of 32x64, k-chunk 32.
// QKV=true:  A = A_arg(x), scatter into g_qkv with padding zeroing
// QKV=false: A = g_ctx (device symbol), plain epilogue to out
// ---------------------------------------------------------------------------
#define KW 20   // k-words (u32, 2 halves each) per smem row, padded 16->20

template <bool QKV>
__global__ __launch_bounds__(256) void gemm_mma_kernel(
    const float* __restrict__ A_arg, const float* __restrict__ W,
    const float* __restrict__ bias, const unsigned int* __restrict__ kpm,
    float* __restrict__ out)
{
    __shared__ unsigned sAh[128 * KW];
    __shared__ unsigned sAl[128 * KW];
    __shared__ unsigned sBh[128 * KW];
    __shared__ unsigned sBl[128 * KW];

    const float* A = QKV ? A_arg : (const float*)g_ctx;

    const int tid  = threadIdx.x;
    const int lane = tid & 31;
    const int warp = tid >> 5;
    const int wm   = warp >> 1;       // 0..3  (M direction, 32 rows each)
    const int wn   = warp & 1;        // 0..1  (N direction, 64 cols each)
    const int m0   = blockIdx.y * 128, n0 = blockIdx.x * 128;

    const int lrow = tid >> 1;        // 0..127
    const int lkof = (tid & 1) * 16;  // 0 or 16 floats within 32-k chunk

    const float* Aptr = A + (size_t)(m0 + lrow) * 1024 + lkof;
    const float* Wptr = W + (size_t)(n0 + lrow) * 1024 + lkof;
    const int swbase = lrow * KW + (tid & 1) * 8;

    float acc[2][8][4];
#pragma unroll
    for (int i = 0; i < 2; i++)
#pragma unroll
        for (int j = 0; j < 8; j++)
#pragma unroll
            for (int c = 0; c < 4; c++) acc[i][j][c] = 0.0f;

    const int r = lane >> 2, cc = lane & 3;

    float4 pa[4], pb[4];
#pragma unroll
    for (int v = 0; v < 4; v++) {
        pa[v] = *(const float4*)(Aptr + v * 4);
        pb[v] = *(const float4*)(Wptr + v * 4);
    }

    for (int kt = 0; kt < 32; kt++) {
        if (kt > 0) __syncthreads();
        // convert + store current chunk
#pragma unroll
        for (int v = 0; v < 4; v++) {
            float rx, ry;
            unsigned h0 = pack_hi(pa[v].x, pa[v].y, rx, ry);
            unsigned l0 = pack_lo(rx, ry);
            unsigned h1 = pack_hi(pa[v].z, pa[v].w, rx, ry);
            unsigned l1 = pack_lo(rx, ry);
            sAh[swbase + v * 2]     = h0;  sAl[swbase + v * 2]     = l0;
            sAh[swbase + v * 2 + 1] = h1;  sAl[swbase + v * 2 + 1] = l1;
            h0 = pack_hi(pb[v].x, pb[v].y, rx, ry);
            l0 = pack_lo(rx, ry);
            h1 = pack_hi(pb[v].z, pb[v].w, rx, ry);
            l1 = pack_lo(rx, ry);
            sBh[swbase + v * 2]     = h0;  sBl[swbase + v * 2]     = l0;
            sBh[swbase + v * 2 + 1] = h1;  sBl[swbase + v * 2 + 1] = l1;
        }
        __syncthreads();
        // prefetch next chunk
        if (kt < 31) {
#pragma unroll
            for (int v = 0; v < 4; v++) {
                pa[v] = *(const float4*)(Aptr + (kt + 1) * 32 + v * 4);
                pb[v] = *(const float4*)(Wptr + (kt + 1) * 32 + v * 4);
            }
        }
        // compute: two k16 steps
#pragma unroll
        for (int half = 0; half < 2; half++) {
            const int kwb = half * 8;
            unsigned ah[2][4], al[2][4];
#pragma unroll
            for (int mi = 0; mi < 2; mi++) {
                const int mrow = wm * 32 + mi * 16 + r;
                ah[mi][0] = sAh[mrow * KW + kwb + cc];
                ah[mi][1] = sAh[(mrow + 8) * KW + kwb + cc];
                ah[mi][2] = sAh[mrow * KW + kwb + 4 + cc];
                ah[mi][3] = sAh[(mrow + 8) * KW + kwb + 4 + cc];
                al[mi][0] = sAl[mrow * KW + kwb + cc];
                al[mi][1] = sAl[(mrow + 8) * KW + kwb + cc];
                al[mi][2] = sAl[mrow * KW + kwb + 4 + cc];
                al[mi][3] = sAl[(mrow + 8) * KW + kwb + 4 + cc];
            }
#pragma unroll
            for (int ni = 0; ni < 8; ni++) {
                const int ncol = wn * 64 + ni * 8 + r;
                const unsigned bh0 = sBh[ncol * KW + kwb + cc];
                const unsigned bh1 = sBh[ncol * KW + kwb + 4 + cc];
                const unsigned bl0 = sBl[ncol * KW + kwb + cc];
                const unsigned bl1 = sBl[ncol * KW + kwb + 4 + cc];
#pragma unroll
                for (int mi = 0; mi < 2; mi++) {
                    mma_bf16(acc[mi][ni], ah[mi], bh0, bh1);
                    mma_bf16(acc[mi][ni], ah[mi], bl0, bl1);
                    mma_bf16(acc[mi][ni], al[mi], bh0, bh1);
                }
            }
        }
    }

    // Epilogue: c0,c1 -> (row, 2c),(row,2c+1); c2,c3 -> (row+8, ...)
#pragma unroll
    for (int mi = 0; mi < 2; mi++) {
        const int mbase = m0 + wm * 32 + mi * 16 + r;
#pragma unroll
        for (int rr = 0; rr < 2; rr++) {
            const int m = mbase + rr * 8;
            if (QKV) {
                const int b = m >> 10, s = m & 1023;
                const bool pad = (kpm[b * 1024 + s] != 0u);
#pragma unroll
                for (int ni = 0; ni < 8; ni++) {
                    const int n = n0 + wn * 64 + ni * 8 + cc * 2;
#pragma unroll
                    for (int e2 = 0; e2 < 2; e2++) {
                        const int c = n + e2;
                        const float v = pad ? 0.0f
                                      : (acc[mi][ni][rr * 2 + e2] + bias[c]);
                        const int which = c >> 10;
                        const int e = c & 1023;
                        const int h = e >> 6, d = e & 63;
                        g_qkv[which * PER + (((b * HH + h) * SS + s) * DKK) + d] = v;
                    }
                }
            } else {
#pragma unroll
                for (int ni = 0; ni < 8; ni++) {
                    const int n = n0 + wn * 64 + ni * 8 + cc * 2;
                    out[(size_t)m * 1024 + n]     = acc[mi][ni][rr * 2]     + bias[n];
                    out[(size_t)m * 1024 + n + 1] = acc[mi][ni][rr * 2 + 1] + bias[n + 1];
                }
            }
        }
    }
}

// ---------------------------------------------------------------------------
// Attention (unchanged from Round 3 — known correct)
// ---------------------------------------------------------------------------
#define TQ 16
#define TK 64
#define KVP 68

__global__ __launch_bounds__(256) void attn_kernel(
    const float* __restrict__ attn_mask, const unsigned int* __restrict__ kpm,
    float* __restrict__ wout)
{
    extern __shared__ float smem[];
    float* scores = smem;                       // TQ * SS
    float* Qs     = scores + TQ * SS;           // TQ * DKK
    float* KVs    = Qs + TQ * DKK;              // TK * KVP
    float* rowl   = KVs + TK * KVP;             // TQ

    const int b = blockIdx.z, h = blockIdx.y, q0 = blockIdx.x * TQ;
    const int tid = threadIdx.x;

    const float* Qg = g_qkv + (((size_t)(b * HH + h) * SS) + q0) * DKK;
    const float* Kg = g_qkv + PER     + ((size_t)(b * HH + h) * SS) * DKK;
    const float* Vg = g_qkv + 2 * PER + ((size_t)(b * HH + h) * SS) * DKK;

    for (int i = tid; i < TQ * DKK; i += 256) Qs[i] = Qg[i];

    const int kc  = tid & 63;
    const int qg0 = tid >> 6;   // 0..3

    // ---- Phase A
    for (int k0 = 0; k0 < SS; k0 += TK) {
        __syncthreads();
        for (int i = tid; i < (TK * DKK) / 4; i += 256) {
            const int base = i * 4;
            const int row = base >> 6, col = base & 63;
            float4 v = *(const float4*)(Kg + (size_t)(k0 + row) * DKK + col);
            *(float4*)&KVs[row * KVP + col] = v;
        }
        __syncthreads();

        const int kglob = k0 + kc;
        const bool kpad = (kpm[b * 1024 + kglob] != 0u);
        float dotv[4] = {0.f, 0.f, 0.f, 0.f};
#pragma unroll
        for (int d = 0; d < DKK; d += 4) {
            float kv[4];
            *(float4*)kv = *(const float4*)&KVs[kc * KVP + d];
#pragma unroll
            for (int u = 0; u < 4; u++) {
                float qv[4];
                *(float4*)qv = *(const float4*)&Qs[(qg0 + 4 * u) * DKK + d];
                dotv[u] += qv[0] * kv[0] + qv[1] * kv[1]
                         + qv[2] * kv[2] + qv[3] * kv[3];
            }
        }
#pragma unroll
        for (int u = 0; u < 4; u++) {
            const int q = qg0 + 4 * u;
            float sval = dotv[u] * 0.125f + attn_mask[(size_t)(q0 + q) * SS + kglob];
            if (kpad) sval = NEGV;
            scores[q * SS + kglob] = sval;
        }
    }
    __syncthreads();

    // ---- Phase B
    {
        const int warp = tid >> 5, lane = tid & 31;
        for (int rr = warp; rr < TQ; rr += 8) {
            float m = -1e30f;
            for (int j = lane; j < SS; j += 32) m = fmaxf(m, scores[rr * SS + j]);
#pragma unroll
            for (int off = 16; off; off >>= 1)
                m = fmaxf(m, __shfl_xor_sync(0xFFFFFFFFu, m, off));
            float l = 0.0f;
            for (int j = lane; j < SS; j += 32) {
                const float e = __expf(scores[rr * SS + j] - m);
                scores[rr * SS + j] = e;
                l += e;
            }
#pragma unroll
            for (int off = 16; off; off >>= 1)
                l += __shfl_xor_sync(0xFFFFFFFFu, l, off);
            if (lane == 0) rowl[rr] = 1.0f / l;
        }
    }
    __syncthreads();

    // ---- Phase C
    {
        const size_t wbase = (((size_t)(b * HH + h) * SS) + q0) * SS;
        for (int idx = tid; idx < (TQ * SS) / 4; idx += 256) {
            const int base = idx * 4;
            const int q = base >> 10, j = base & 1023;
            float4 wv = *(const float4*)&scores[base];
            const float rl = rowl[q];
            wv.x *= rl; wv.y *= rl; wv.z *= rl; wv.w *= rl;
            *(float4*)&scores[base] = wv;
            *(float4*)&wout[wbase + (size_t)q * SS + j] = wv;
        }
    }

    // ---- Phase D
    {
        const int d = kc;
        float acc[4] = {0.f, 0.f, 0.f, 0.f};
        for (int k0 = 0; k0 < SS; k0 += TK) {
            __syncthreads();
            for (int i = tid; i < (TK * DKK) / 4; i += 256) {
                const int base = i * 4;
                const int row = base >> 6, col = base & 63;
                float4 v = *(const float4*)(Vg + (size_t)(k0 + row) * DKK + col);
                *(float4*)&KVs[row * KVP + col] = v;
            }
            __syncthreads();
#pragma unroll
            for (int kj = 0; kj < TK; kj += 4) {
                float w0[4], w1[4], w2[4], w3[4];
                *(float4*)w0 = *(const float4*)&scores[(qg0 +  0) * SS + k0 + kj];
                *(float4*)w1 = *(const float4*)&scores[(qg0 +  4) * SS + k0 + kj];
                *(float4*)w2 = *(const float4*)&scores[(qg0 +  8) * SS + k0 + kj];
                *(float4*)w3 = *(const float4*)&scores[(qg0 + 12) * SS + k0 + kj];
#pragma unroll
                for (int j = 0; j < 4; j++) {
                    const float vv = KVs[(kj + j) * KVP + d];
                    acc[0] += w0[j] * vv;
                    acc[1] += w1[j] * vv;
                    acc[2] += w2[j] * vv;
                    acc[3] += w3[j] * vv;
                }
            }
        }
#pragma unroll
        for (int u = 0; u < 4; u++) {
            const int q = qg0 + 4 * u;
            g_ctx[((size_t)(b * SS + q0 + q)) * EE + h * DKK + d] = acc[u];
        }
    }
}

// ---------------------------------------------------------------------------
extern "C" void kernel_launch(void* const* d_in, const int* in_sizes, int n_in,
                              void* d_out, int out_size)
{
    const float*        x         = (const float*)d_in[0];
    const float*        attn_mask = (const float*)d_in[1];
    const unsigned int* kpm       = (const unsigned int*)d_in[2];
    const float*        qkv_w     = (const float*)d_in[3];
    const float*        qkv_b     = (const float*)d_in[4];
    const float*        out_w     = (const float*)d_in[5];
    const float*        out_b     = (const float*)d_in[6];

    float* out  = (float*)d_out;
    float* wout = out + (size_t)BB * SS * EE;

    const int attn_smem = (TQ * SS + TQ * DKK + TK * KVP + TQ) * 4;
    cudaFuncSetAttribute(attn_kernel,
                         cudaFuncAttributeMaxDynamicSharedMemorySize, attn_smem);

    // 1) QKV projection -> g_qkv
    gemm_mma_kernel<true><<<dim3(24, 32), 256>>>(x, qkv_w, qkv_b, kpm, nullptr);

    // 2) Attention
    attn_kernel<<<dim3(SS / TQ, HH, BB), 256, attn_smem>>>(attn_mask, kpm, wout);

    // 3) Output projection
    gemm_mma_kernel<false><<<dim3(8, 32), 256>>>(nullptr, out_w, out_b, nullptr, out);
}

// round 5
// speedup vs baseline: 2.3848x; 1.8270x over previous
#include <cuda_runtime.h>
#include <cuda_bf16.h>
#include <math.h>

// Problem constants
#define BB 4
#define SS 1024
#define EE 1024
#define HH 16
#define DKK 64
#define PER (BB * HH * SS * DKK)
#define NEGV (-10000.0f)

// Scratch
__device__ float g_qkv[3 * BB * HH * SS * DKK];   // q|k|v, each [B,H,S,DK]
__device__ float g_ctx[BB * SS * EE];             // [B,S,E]
__device__ float g_m[BB * HH * SS];               // row max
__device__ float g_linv[BB * HH * SS];            // 1/row denom

// ---------------------------------------------------------------------------
// bf16 split-precision helpers
// ---------------------------------------------------------------------------
__device__ __forceinline__ void mma_bf16(float* d, const unsigned* a,
                                         unsigned b0, unsigned b1)
{
    asm("mma.sync.aligned.m16n8k16.row.col.f32.bf16.bf16.f32 "
        "{%0,%1,%2,%3}, {%4,%5,%6,%7}, {%8,%9}, {%0,%1,%2,%3};"
        : "+f"(d[0]), "+f"(d[1]), "+f"(d[2]), "+f"(d[3])
        : "r"(a[0]), "r"(a[1]), "r"(a[2]), "r"(a[3]), "r"(b0), "r"(b1));
}

__device__ __forceinline__ unsigned pack_hi(float x, float y,
                                            float& rx, float& ry)
{
    __nv_bfloat162 t = __floats2bfloat162_rn(x, y);
    rx = x - __bfloat162float(t.x);
    ry = y - __bfloat162float(t.y);
    unsigned u; *(__nv_bfloat162*)&u = t; return u;
}
__device__ __forceinline__ unsigned pack_lo(float rx, float ry)
{
    __nv_bfloat162 t = __floats2bfloat162_rn(rx, ry);
    unsigned u; *(__nv_bfloat162*)&u = t; return u;
}

// ---------------------------------------------------------------------------
// Tensor-core GEMM (unchanged from Round 4 — known good)
// ---------------------------------------------------------------------------
#define KW 20

template <bool QKV>
__global__ __launch_bounds__(256) void gemm_mma_kernel(
    const float* __restrict__ A_arg, const float* __restrict__ W,
    const float* __restrict__ bias, const unsigned int* __restrict__ kpm,
    float* __restrict__ out)
{
    __shared__ unsigned sAh[128 * KW];
    __shared__ unsigned sAl[128 * KW];
    __shared__ unsigned sBh[128 * KW];
    __shared__ unsigned sBl[128 * KW];

    const float* A = QKV ? A_arg : (const float*)g_ctx;

    const int tid  = threadIdx.x;
    const int lane = tid & 31;
    const int warp = tid >> 5;
    const int wm   = warp >> 1;
    const int wn   = warp & 1;
    const int m0   = blockIdx.y * 128, n0 = blockIdx.x * 128;

    const int lrow = tid >> 1;
    const int lkof = (tid & 1) * 16;

    const float* Aptr = A + (size_t)(m0 + lrow) * 1024 + lkof;
    const float* Wptr = W + (size_t)(n0 + lrow) * 1024 + lkof;
    const int swbase = lrow * KW + (tid & 1) * 8;

    float acc[2][8][4];
#pragma unroll
    for (int i = 0; i < 2; i++)
#pragma unroll
        for (int j = 0; j < 8; j++)
#pragma unroll
            for (int c = 0; c < 4; c++) acc[i][j][c] = 0.0f;

    const int r = lane >> 2, cc = lane & 3;

    float4 pa[4], pb[4];
#pragma unroll
    for (int v = 0; v < 4; v++) {
        pa[v] = *(const float4*)(Aptr + v * 4);
        pb[v] = *(const float4*)(Wptr + v * 4);
    }

    for (int kt = 0; kt < 32; kt++) {
        if (kt > 0) __syncthreads();
#pragma unroll
        for (int v = 0; v < 4; v++) {
            float rx, ry;
            unsigned h0 = pack_hi(pa[v].x, pa[v].y, rx, ry);
            unsigned l0 = pack_lo(rx, ry);
            unsigned h1 = pack_hi(pa[v].z, pa[v].w, rx, ry);
            unsigned l1 = pack_lo(rx, ry);
            sAh[swbase + v * 2]     = h0;  sAl[swbase + v * 2]     = l0;
            sAh[swbase + v * 2 + 1] = h1;  sAl[swbase + v * 2 + 1] = l1;
            h0 = pack_hi(pb[v].x, pb[v].y, rx, ry);
            l0 = pack_lo(rx, ry);
            h1 = pack_hi(pb[v].z, pb[v].w, rx, ry);
            l1 = pack_lo(rx, ry);
            sBh[swbase + v * 2]     = h0;  sBl[swbase + v * 2]     = l0;
            sBh[swbase + v * 2 + 1] = h1;  sBl[swbase + v * 2 + 1] = l1;
        }
        __syncthreads();
        if (kt < 31) {
#pragma unroll
            for (int v = 0; v < 4; v++) {
                pa[v] = *(const float4*)(Aptr + (kt + 1) * 32 + v * 4);
                pb[v] = *(const float4*)(Wptr + (kt + 1) * 32 + v * 4);
            }
        }
#pragma unroll
        for (int half = 0; half < 2; half++) {
            const int kwb = half * 8;
            unsigned ah[2][4], al[2][4];
#pragma unroll
            for (int mi = 0; mi < 2; mi++) {
                const int mrow = wm * 32 + mi * 16 + r;
                ah[mi][0] = sAh[mrow * KW + kwb + cc];
                ah[mi][1] = sAh[(mrow + 8) * KW + kwb + cc];
                ah[mi][2] = sAh[mrow * KW + kwb + 4 + cc];
                ah[mi][3] = sAh[(mrow + 8) * KW + kwb + 4 + cc];
                al[mi][0] = sAl[mrow * KW + kwb + cc];
                al[mi][1] = sAl[(mrow + 8) * KW + kwb + cc];
                al[mi][2] = sAl[mrow * KW + kwb + 4 + cc];
                al[mi][3] = sAl[(mrow + 8) * KW + kwb + 4 + cc];
            }
#pragma unroll
            for (int ni = 0; ni < 8; ni++) {
                const int ncol = wn * 64 + ni * 8 + r;
                const unsigned bh0 = sBh[ncol * KW + kwb + cc];
                const unsigned bh1 = sBh[ncol * KW + kwb + 4 + cc];
                const unsigned bl0 = sBl[ncol * KW + kwb + cc];
                const unsigned bl1 = sBl[ncol * KW + kwb + 4 + cc];
#pragma unroll
                for (int mi = 0; mi < 2; mi++) {
                    mma_bf16(acc[mi][ni], ah[mi], bh0, bh1);
                    mma_bf16(acc[mi][ni], ah[mi], bl0, bl1);
                    mma_bf16(acc[mi][ni], al[mi], bh0, bh1);
                }
            }
        }
    }

#pragma unroll
    for (int mi = 0; mi < 2; mi++) {
        const int mbase = m0 + wm * 32 + mi * 16 + r;
#pragma unroll
        for (int rr = 0; rr < 2; rr++) {
            const int m = mbase + rr * 8;
            if (QKV) {
                const int b = m >> 10, s = m & 1023;
                const bool pad = (kpm[b * 1024 + s] != 0u);
#pragma unroll
                for (int ni = 0; ni < 8; ni++) {
                    const int n = n0 + wn * 64 + ni * 8 + cc * 2;
#pragma unroll
                    for (int e2 = 0; e2 < 2; e2++) {
                        const int c = n + e2;
                        const float v = pad ? 0.0f
                                      : (acc[mi][ni][rr * 2 + e2] + bias[c]);
                        const int which = c >> 10;
                        const int e = c & 1023;
                        const int h = e >> 6, d = e & 63;
                        g_qkv[which * PER + (((b * HH + h) * SS + s) * DKK) + d] = v;
                    }
                }
            } else {
#pragma unroll
                for (int ni = 0; ni < 8; ni++) {
                    const int n = n0 + wn * 64 + ni * 8 + cc * 2;
                    out[(size_t)m * 1024 + n]     = acc[mi][ni][rr * 2]     + bias[n];
                    out[(size_t)m * 1024 + n + 1] = acc[mi][ni][rr * 2 + 1] + bias[n + 1];
                }
            }
        }
    }
}

// ---------------------------------------------------------------------------
// Attention Pass A: raw scores -> wout, row max/denom -> g_m/g_linv.
// CTA = (b, h, 128 q rows). Warp w owns q rows w*16 + r, + 8 (r = lane>>2).
// smem (u32): sQh[4608] sQl[4608] sKh[4608] sKl[4608] sKp[128]
// ---------------------------------------------------------------------------
#define QS 36   // 32 k-words padded to 36; bank = 4r + cc, conflict-free

__global__ __launch_bounds__(256) void attn_score_kernel(
    const unsigned int* __restrict__ kpm, float* __restrict__ wout)
{
    extern __shared__ unsigned sm[];
    unsigned* sQh = sm;
    unsigned* sQl = sQh + 128 * QS;
    unsigned* sKh = sQl + 128 * QS;
    unsigned* sKl = sKh + 128 * QS;
    unsigned* sKp = sKl + 128 * QS;

    const int b = blockIdx.z, h = blockIdx.y, q0 = blockIdx.x * 128;
    const int tid = threadIdx.x, lane = tid & 31, w = tid >> 5;
    const int r = lane >> 2, cc = lane & 3;

    const float* Qg = g_qkv + ((size_t)(b * HH + h) * SS + q0) * DKK;
    const float* Kg = g_qkv + PER + ((size_t)(b * HH + h) * SS) * DKK;

    // Load + convert Q tile (128x64)
    for (int i = tid; i < 2048; i += 256) {
        const int row = i >> 4, c4 = (i & 15) * 4;
        float4 v = *(const float4*)(Qg + (size_t)row * DKK + c4);
        float rx, ry;
        unsigned h0 = pack_hi(v.x, v.y, rx, ry); unsigned l0 = pack_lo(rx, ry);
        unsigned h1 = pack_hi(v.z, v.w, rx, ry); unsigned l1 = pack_lo(rx, ry);
        const int base = row * QS + (c4 >> 1);
        sQh[base] = h0; sQh[base + 1] = h1;
        sQl[base] = l0; sQl[base + 1] = l1;
    }
    __syncthreads();

    // Extract Q fragments (reused across all key tiles)
    const int qr = w * 16 + r;
    unsigned aQh[4][4], aQl[4][4];
#pragma unroll
    for (int ks = 0; ks < 4; ks++) {
        const int bw = ks * 8 + cc;
        aQh[ks][0] = sQh[qr * QS + bw];
        aQh[ks][1] = sQh[(qr + 8) * QS + bw];
        aQh[ks][2] = sQh[qr * QS + bw + 4];
        aQh[ks][3] = sQh[(qr + 8) * QS + bw + 4];
        aQl[ks][0] = sQl[qr * QS + bw];
        aQl[ks][1] = sQl[(qr + 8) * QS + bw];
        aQl[ks][2] = sQl[qr * QS + bw + 4];
        aQl[ks][3] = sQl[(qr + 8) * QS + bw + 4];
    }

    const int row0 = q0 + qr, row1 = row0 + 8;
    float* wrow0 = wout + ((size_t)(b * HH + h) * SS + row0) * SS;
    float* wrow1 = wout + ((size_t)(b * HH + h) * SS + row1) * SS;

    float m_run[2] = {-1e30f, -1e30f};
    float l_run[2] = {0.0f, 0.0f};

    for (int nt = 0; nt < 8; nt++) {
        __syncthreads();
        for (int i = tid; i < 2048; i += 256) {
            const int row = i >> 4, c4 = (i & 15) * 4;
            float4 v = *(const float4*)(Kg + (size_t)(nt * 128 + row) * DKK + c4);
            float rx, ry;
            unsigned h0 = pack_hi(v.x, v.y, rx, ry); unsigned l0 = pack_lo(rx, ry);
            unsigned h1 = pack_hi(v.z, v.w, rx, ry); unsigned l1 = pack_lo(rx, ry);
            const int base = row * QS + (c4 >> 1);
            sKh[base] = h0; sKh[base + 1] = h1;
            sKl[base] = l0; sKl[base + 1] = l1;
        }
        if (tid < 128) sKp[tid] = kpm[b * 1024 + nt * 128 + tid];
        __syncthreads();

        float acc[16][4];
#pragma unroll
        for (int ni = 0; ni < 16; ni++)
#pragma unroll
            for (int c = 0; c < 4; c++) acc[ni][c] = 0.0f;

#pragma unroll
        for (int ks = 0; ks < 4; ks++) {
            const int bw = ks * 8 + cc;
#pragma unroll
            for (int ni = 0; ni < 16; ni++) {
                const int krow = ni * 8 + r;
                const unsigned bh0 = sKh[krow * QS + bw];
                const unsigned bh1 = sKh[krow * QS + bw + 4];
                const unsigned bl0 = sKl[krow * QS + bw];
                const unsigned bl1 = sKl[krow * QS + bw + 4];
                mma_bf16(acc[ni], aQh[ks], bh0, bh1);
                mma_bf16(acc[ni], aQh[ks], bl0, bl1);
                mma_bf16(acc[ni], aQl[ks], bh0, bh1);
            }
        }

        // scale + causal(add) + kpad(replace), store raw scores
#pragma unroll
        for (int ni = 0; ni < 16; ni++) {
            const int colb = ni * 8 + cc * 2;
            const int col = nt * 128 + colb;
#pragma unroll
            for (int e = 0; e < 2; e++) {
                const bool pad = (sKp[colb + e] != 0u);
                float s0 = acc[ni][e] * 0.125f;
                if (col + e > row0) s0 += NEGV;
                if (pad) s0 = NEGV;
                acc[ni][e] = s0;
                float s1 = acc[ni][2 + e] * 0.125f;
                if (col + e > row1) s1 += NEGV;
                if (pad) s1 = NEGV;
                acc[ni][2 + e] = s1;
            }
            *(float2*)(wrow0 + col) = make_float2(acc[ni][0], acc[ni][1]);
            *(float2*)(wrow1 + col) = make_float2(acc[ni][2], acc[ni][3]);
        }

        // online stats
        float tm0 = -1e30f, tm1 = -1e30f;
#pragma unroll
        for (int ni = 0; ni < 16; ni++) {
            tm0 = fmaxf(tm0, fmaxf(acc[ni][0], acc[ni][1]));
            tm1 = fmaxf(tm1, fmaxf(acc[ni][2], acc[ni][3]));
        }
        tm0 = fmaxf(tm0, __shfl_xor_sync(0xFFFFFFFFu, tm0, 1));
        tm0 = fmaxf(tm0, __shfl_xor_sync(0xFFFFFFFFu, tm0, 2));
        tm1 = fmaxf(tm1, __shfl_xor_sync(0xFFFFFFFFu, tm1, 1));
        tm1 = fmaxf(tm1, __shfl_xor_sync(0xFFFFFFFFu, tm1, 2));
        const float nm0 = fmaxf(m_run[0], tm0);
        const float nm1 = fmaxf(m_run[1], tm1);
        float s0 = 0.0f, s1 = 0.0f;
#pragma unroll
        for (int ni = 0; ni < 16; ni++) {
            s0 += __expf(acc[ni][0] - nm0) + __expf(acc[ni][1] - nm0);
            s1 += __expf(acc[ni][2] - nm1) + __expf(acc[ni][3] - nm1);
        }
        s0 += __shfl_xor_sync(0xFFFFFFFFu, s0, 1);
        s0 += __shfl_xor_sync(0xFFFFFFFFu, s0, 2);
        s1 += __shfl_xor_sync(0xFFFFFFFFu, s1, 1);
        s1 += __shfl_xor_sync(0xFFFFFFFFu, s1, 2);
        l_run[0] = l_run[0] * __expf(m_run[0] - nm0) + s0;
        l_run[1] = l_run[1] * __expf(m_run[1] - nm1) + s1;
        m_run[0] = nm0; m_run[1] = nm1;
    }

    if (cc == 0) {
        const int sbase = (b * HH + h) * SS;
        g_m[sbase + row0] = m_run[0];
        g_m[sbase + row1] = m_run[1];
        g_linv[sbase + row0] = 1.0f / l_run[0];
        g_linv[sbase + row1] = 1.0f / l_run[1];
    }
}

// ---------------------------------------------------------------------------
// Attention Pass B: w = exp(s-m)/l (write back), ctx = W @ V via split MMA.
// CTA = (b, h, 128 q rows). Warp w owns q rows w*16 + r, +8; all 64 dims.
// smem (u32): sWh[8704] sWl[8704] sVh[4352] sVl[4352] sM[128] sLi[128]
// ---------------------------------------------------------------------------
#define WS 68   // 64 k-words padded to 68

__global__ __launch_bounds__(256) void attn_av_kernel(float* __restrict__ wout)
{
    extern __shared__ unsigned sm[];
    unsigned* sWh = sm;
    unsigned* sWl = sWh + 128 * WS;
    unsigned* sVh = sWl + 128 * WS;          // 64 rows (dims) x 68 words
    unsigned* sVl = sVh + 64 * WS;
    float*    sM  = (float*)(sVl + 64 * WS);
    float*    sLi = sM + 128;

    const int b = blockIdx.z, h = blockIdx.y, q0 = blockIdx.x * 128;
    const int tid = threadIdx.x, lane = tid & 31, w = tid >> 5;
    const int r = lane >> 2, cc = lane & 3;

    const float* Vg = g_qkv + 2 * PER + ((size_t)(b * HH + h) * SS) * DKK;
    float* wbase = wout + ((size_t)(b * HH + h) * SS + q0) * SS;

    if (tid < 128) {
        const int sbase = (b * HH + h) * SS + q0;
        sM[tid]  = g_m[sbase + tid];
        sLi[tid] = g_linv[sbase + tid];
    }
    __syncthreads();

    float acc[8][4];
#pragma unroll
    for (int ni = 0; ni < 8; ni++)
#pragma unroll
        for (int c = 0; c < 4; c++) acc[ni][c] = 0.0f;

    const int qr = w * 16 + r;

    for (int kt = 0; kt < 8; kt++) {
        if (kt > 0) __syncthreads();
        // scores tile -> weights (write back) + bf16 hi/lo smem
        for (int i = tid; i < 4096; i += 256) {
            const int row = i >> 5, c4 = (i & 31) * 4;
            float* p = wbase + (size_t)row * SS + kt * 128 + c4;
            float4 s = *(const float4*)p;
            const float mm = sM[row], li = sLi[row];
            float4 wv;
            wv.x = __expf(s.x - mm) * li;
            wv.y = __expf(s.y - mm) * li;
            wv.z = __expf(s.z - mm) * li;
            wv.w = __expf(s.w - mm) * li;
            *(float4*)p = wv;
            float rx, ry;
            unsigned h0 = pack_hi(wv.x, wv.y, rx, ry); unsigned l0 = pack_lo(rx, ry);
            unsigned h1 = pack_hi(wv.z, wv.w, rx, ry); unsigned l1 = pack_lo(rx, ry);
            const int base = row * WS + (c4 >> 1);
            sWh[base] = h0; sWh[base + 1] = h1;
            sWl[base] = l0; sWl[base + 1] = l1;
        }
        // V tile transposed: sVt[d][key]
        {
            __nv_bfloat16* tVh = (__nv_bfloat16*)sVh;
            __nv_bfloat16* tVl = (__nv_bfloat16*)sVl;
            for (int i = tid; i < 2048; i += 256) {
                const int key = i >> 4, d4 = (i & 15) * 4;
                float4 v = *(const float4*)(Vg + (size_t)(kt * 128 + key) * DKK + d4);
                float f[4] = {v.x, v.y, v.z, v.w};
#pragma unroll
                for (int j = 0; j < 4; j++) {
                    __nv_bfloat16 hb = __float2bfloat16(f[j]);
                    float lo = f[j] - __bfloat162float(hb);
                    tVh[(d4 + j) * (2 * WS) + key] = hb;
                    tVl[(d4 + j) * (2 * WS) + key] = __float2bfloat16(lo);
                }
            }
        }
        __syncthreads();

#pragma unroll
        for (int ks = 0; ks < 8; ks++) {
            const int bw = ks * 8 + cc;
            unsigned ah[4], al[4];
            ah[0] = sWh[qr * WS + bw];
            ah[1] = sWh[(qr + 8) * WS + bw];
            ah[2] = sWh[qr * WS + bw + 4];
            ah[3] = sWh[(qr + 8) * WS + bw + 4];
            al[0] = sWl[qr * WS + bw];
            al[1] = sWl[(qr + 8) * WS + bw];
            al[2] = sWl[qr * WS + bw + 4];
            al[3] = sWl[(qr + 8) * WS + bw + 4];
#pragma unroll
            for (int ni = 0; ni < 8; ni++) {
                const int vrow = ni * 8 + r;
                const unsigned bh0 = sVh[vrow * WS + bw];
                const unsigned bh1 = sVh[vrow * WS + bw + 4];
                const unsigned bl0 = sVl[vrow * WS + bw];
                const unsigned bl1 = sVl[vrow * WS + bw + 4];
                mma_bf16(acc[ni], ah, bh0, bh1);
                mma_bf16(acc[ni], ah, bl0, bl1);
                mma_bf16(acc[ni], al, bh0, bh1);
            }
        }
    }

    // ctx epilogue
    float* c0 = g_ctx + ((size_t)(b * SS + q0 + qr)) * EE + h * DKK;
    float* c1 = g_ctx + ((size_t)(b * SS + q0 + qr + 8)) * EE + h * DKK;
#pragma unroll
    for (int ni = 0; ni < 8; ni++) {
        const int d0 = ni * 8 + cc * 2;
        *(float2*)(c0 + d0) = make_float2(acc[ni][0], acc[ni][1]);
        *(float2*)(c1 + d0) = make_float2(acc[ni][2], acc[ni][3]);
    }
}

// ---------------------------------------------------------------------------
extern "C" void kernel_launch(void* const* d_in, const int* in_sizes, int n_in,
                              void* d_out, int out_size)
{
    const float*        x         = (const float*)d_in[0];
    const unsigned int* kpm       = (const unsigned int*)d_in[2];
    const float*        qkv_w     = (const float*)d_in[3];
    const float*        qkv_b     = (const float*)d_in[4];
    const float*        out_w     = (const float*)d_in[5];
    const float*        out_b     = (const float*)d_in[6];

    float* out  = (float*)d_out;
    float* wout = out + (size_t)BB * SS * EE;

    const int scoreSmem = (4 * 128 * QS + 128) * 4;                 // ~74.2 KB
    const int avSmem    = (2 * 128 * WS + 2 * 64 * WS + 256) * 4;   // ~105.5 KB
    cudaFuncSetAttribute(attn_score_kernel,
                         cudaFuncAttributeMaxDynamicSharedMemorySize, scoreSmem);
    cudaFuncSetAttribute(attn_av_kernel,
                         cudaFuncAttributeMaxDynamicSharedMemorySize, avSmem);

    // 1) QKV projection -> g_qkv
    gemm_mma_kernel<true><<<dim3(24, 32), 256>>>(x, qkv_w, qkv_b, kpm, nullptr);

    // 2a) Scores + online stats
    attn_score_kernel<<<dim3(8, HH, BB), 256, scoreSmem>>>(kpm, wout);

    // 2b) Softmax weights + ctx = W @ V
    attn_av_kernel<<<dim3(8, HH, BB), 256, avSmem>>>(wout);

    // 3) Output projection
    gemm_mma_kernel<false><<<dim3(8, 32), 256>>>(nullptr, out_w, out_b, nullptr, out);
}

// round 6
// speedup vs baseline: 3.2360x; 1.3569x over previous
#include <cuda_runtime.h>
#include <cuda_bf16.h>
#include <math.h>

// Problem constants
#define BB 4
#define SS 1024
#define EE 1024
#define HH 16
#define DKK 64
#define PER (BB * HH * SS * DKK)   // 4194304 elems per q/k/v tensor
#define NEGV (-10000.0f)

// ---------------------------------------------------------------------------
// Scratch: bf16 hi/lo pairs, packed as u32 words (2 bf16 along k) for GEMMs
// ---------------------------------------------------------------------------
__device__ unsigned g_xh[4096 * 512],  g_xl[4096 * 512];    // x
__device__ unsigned g_qwh[3072 * 512], g_qwl[3072 * 512];   // qkv_w
__device__ unsigned g_owh[1024 * 512], g_owl[1024 * 512];   // out_w
__device__ unsigned g_cth[4096 * 512], g_ctl[4096 * 512];   // ctx [B*S, E]
__device__ __nv_bfloat16 g_qh[3 * PER], g_ql[3 * PER];      // q|k|v hi/lo
__device__ float g_m[BB * HH * SS];                         // row max
__device__ float g_linv[BB * HH * SS];                      // 1/row denom

// ---------------------------------------------------------------------------
// helpers
// ---------------------------------------------------------------------------
__device__ __forceinline__ void mma_bf16(float* d, const unsigned* a,
                                         unsigned b0, unsigned b1)
{
    asm("mma.sync.aligned.m16n8k16.row.col.f32.bf16.bf16.f32 "
        "{%0,%1,%2,%3}, {%4,%5,%6,%7}, {%8,%9}, {%0,%1,%2,%3};"
        : "+f"(d[0]), "+f"(d[1]), "+f"(d[2]), "+f"(d[3])
        : "r"(a[0]), "r"(a[1]), "r"(a[2]), "r"(a[3]), "r"(b0), "r"(b1));
}

__device__ __forceinline__ unsigned pack_hi(float x, float y,
                                            float& rx, float& ry)
{
    __nv_bfloat162 t = __floats2bfloat162_rn(x, y);
    rx = x - __bfloat162float(t.x);
    ry = y - __bfloat162float(t.y);
    unsigned u; *(__nv_bfloat162*)&u = t; return u;
}
__device__ __forceinline__ unsigned pack_lo(float rx, float ry)
{
    __nv_bfloat162 t = __floats2bfloat162_rn(rx, ry);
    unsigned u; *(__nv_bfloat162*)&u = t; return u;
}

__device__ __forceinline__ void cpa16(unsigned dst, const void* src)
{
    asm volatile("cp.async.cg.shared.global [%0], [%1], 16;"
                 :: "r"(dst), "l"(src));
}
__device__ __forceinline__ void cpa_commit()
{
    asm volatile("cp.async.commit_group;");
}
__device__ __forceinline__ void cpa_wait0()
{
    asm volatile("cp.async.wait_group 0;");
}

// ---------------------------------------------------------------------------
// Prep: fp32 -> bf16 hi/lo word arrays. which: 0=x, 1=qkv_w, 2=out_w
// ---------------------------------------------------------------------------
__global__ void cvt_kernel(const float* __restrict__ src, int which, int n4)
{
    unsigned* dh = (which == 0) ? g_xh : (which == 1) ? g_qwh : g_owh;
    unsigned* dl = (which == 0) ? g_xl : (which == 1) ? g_qwl : g_owl;
    const int i = blockIdx.x * blockDim.x + threadIdx.x;
    if (i < n4) {
        float4 v = ((const float4*)src)[i];
        float rx, ry;
        unsigned h0 = pack_hi(v.x, v.y, rx, ry);
        unsigned l0 = pack_lo(rx, ry);
        unsigned h1 = pack_hi(v.z, v.w, rx, ry);
        unsigned l1 = pack_lo(rx, ry);
        dh[2 * i] = h0; dh[2 * i + 1] = h1;
        dl[2 * i] = l0; dl[2 * i + 1] = l1;
    }
}

// ---------------------------------------------------------------------------
// GEMM: C(M,N) = A @ W^T + bias, bf16 hi/lo operands preconverted in gmem.
// 128x128 tile, 8 warps 32x64, cp.async double-buffered, 2 CTAs/SM target.
// MODE 0: A=x, W=qkv_w, epilogue scatter -> g_qh/g_ql (pad-zeroed)
// MODE 1: A=ctx, W=out_w, epilogue fp32 -> out
// ---------------------------------------------------------------------------
#define KW 20   // 16 data words + 4 pad per 32-float k-chunk row

template <int MODE>
__global__ __launch_bounds__(256, 2) void gemm_bf16_kernel(
    const float* __restrict__ bias, const unsigned int* __restrict__ kpm,
    float* __restrict__ out)
{
    extern __shared__ unsigned dynsm[];   // [2 stages][4 arrays][2560 words]
    const unsigned *Ah, *Al, *Wh, *Wl;
    if (MODE == 0) { Ah = g_xh;  Al = g_xl;  Wh = g_qwh; Wl = g_qwl; }
    else           { Ah = g_cth; Al = g_ctl; Wh = g_owh; Wl = g_owl; }

    const int tid = threadIdx.x, lane = tid & 31, warp = tid >> 5;
    const int wm = warp >> 1, wn = warp & 1;
    const int m0 = blockIdx.y * 128, n0 = blockIdx.x * 128;
    const int r = lane >> 2, cc = lane & 3;

    const unsigned sbase = (unsigned)__cvta_generic_to_shared(dynsm);

    // gmem->smem mapping: 512 uint4-chunks per array; thread owns 2 chunks
    const int c0 = tid, c1 = tid + 256;
    const int row0 = c0 >> 2, off0 = (c0 & 3) * 4;
    const int row1 = c1 >> 2, off1 = (c1 & 3) * 4;
    const unsigned so0 = (unsigned)(row0 * KW + off0) * 4u;
    const unsigned so1 = (unsigned)(row1 * KW + off1) * 4u;
    const size_t ga0 = (size_t)(m0 + row0) * 512 + off0;
    const size_t ga1 = (size_t)(m0 + row1) * 512 + off1;
    const size_t gb0 = (size_t)(n0 + row0) * 512 + off0;
    const size_t gb1 = (size_t)(n0 + row1) * 512 + off1;

    float acc[2][8][4];
#pragma unroll
    for (int i = 0; i < 2; i++)
#pragma unroll
        for (int j = 0; j < 8; j++)
#pragma unroll
            for (int c = 0; c < 4; c++) acc[i][j][c] = 0.0f;

#define ISSUE(kt, st) do {                                                  \
    const int kk_ = (kt) * 16;                                              \
    const unsigned sb_ = sbase + (unsigned)(st) * 40960u;                   \
    cpa16(sb_ +      0u + so0, Ah + ga0 + kk_);                             \
    cpa16(sb_ +      0u + so1, Ah + ga1 + kk_);                             \
    cpa16(sb_ + 10240u + so0, Al + ga0 + kk_);                              \
    cpa16(sb_ + 10240u + so1, Al + ga1 + kk_);                              \
    cpa16(sb_ + 20480u + so0, Wh + gb0 + kk_);                              \
    cpa16(sb_ + 20480u + so1, Wh + gb1 + kk_);                              \
    cpa16(sb_ + 30720u + so0, Wl + gb0 + kk_);                              \
    cpa16(sb_ + 30720u + so1, Wl + gb1 + kk_);                              \
    cpa_commit(); } while (0)

    ISSUE(0, 0);

    for (int kt = 0; kt < 32; kt++) {
        cpa_wait0();
        __syncthreads();
        if (kt < 31) ISSUE(kt + 1, (kt + 1) & 1);

        const unsigned* pAh = dynsm + (kt & 1) * 10240 + 0 * 2560;
        const unsigned* pAl = dynsm + (kt & 1) * 10240 + 1 * 2560;
        const unsigned* pBh = dynsm + (kt & 1) * 10240 + 2 * 2560;
        const unsigned* pBl = dynsm + (kt & 1) * 10240 + 3 * 2560;

#pragma unroll
        for (int half = 0; half < 2; half++) {
            const int kwb = half * 8;
            unsigned ah[2][4], al[2][4];
#pragma unroll
            for (int mi = 0; mi < 2; mi++) {
                const int mrow = wm * 32 + mi * 16 + r;
                ah[mi][0] = pAh[mrow * KW + kwb + cc];
                ah[mi][1] = pAh[(mrow + 8) * KW + kwb + cc];
                ah[mi][2] = pAh[mrow * KW + kwb + 4 + cc];
                ah[mi][3] = pAh[(mrow + 8) * KW + kwb + 4 + cc];
                al[mi][0] = pAl[mrow * KW + kwb + cc];
                al[mi][1] = pAl[(mrow + 8) * KW + kwb + cc];
                al[mi][2] = pAl[mrow * KW + kwb + 4 + cc];
                al[mi][3] = pAl[(mrow + 8) * KW + kwb + 4 + cc];
            }
#pragma unroll
            for (int ni = 0; ni < 8; ni++) {
                const int ncol = wn * 64 + ni * 8 + r;
                const unsigned bh0 = pBh[ncol * KW + kwb + cc];
                const unsigned bh1 = pBh[ncol * KW + kwb + 4 + cc];
                const unsigned bl0 = pBl[ncol * KW + kwb + cc];
                const unsigned bl1 = pBl[ncol * KW + kwb + 4 + cc];
#pragma unroll
                for (int mi = 0; mi < 2; mi++) {
                    mma_bf16(acc[mi][ni], ah[mi], bh0, bh1);
                    mma_bf16(acc[mi][ni], ah[mi], bl0, bl1);
                    mma_bf16(acc[mi][ni], al[mi], bh0, bh1);
                }
            }
        }
        __syncthreads();
    }
#undef ISSUE

#pragma unroll
    for (int mi = 0; mi < 2; mi++) {
        const int mbase = m0 + wm * 32 + mi * 16 + r;
#pragma unroll
        for (int rr = 0; rr < 2; rr++) {
            const int m = mbase + rr * 8;
            if (MODE == 0) {
                const int b = m >> 10, s = m & 1023;
                const bool pad = (kpm[b * 1024 + s] != 0u);
#pragma unroll
                for (int ni = 0; ni < 8; ni++) {
                    const int c = n0 + wn * 64 + ni * 8 + cc * 2;
                    const float v0 = pad ? 0.0f : (acc[mi][ni][rr * 2]     + bias[c]);
                    const float v1 = pad ? 0.0f : (acc[mi][ni][rr * 2 + 1] + bias[c + 1]);
                    const int which = c >> 10;
                    const int e = c & 1023;
                    const int hh = e >> 6, d = e & 63;
                    const size_t idx = (size_t)which * PER
                                     + ((size_t)(b * HH + hh) * SS + s) * DKK + d;
                    __nv_bfloat162 hv, lv;
                    hv.x = __float2bfloat16(v0);
                    lv.x = __float2bfloat16(v0 - __bfloat162float(hv.x));
                    hv.y = __float2bfloat16(v1);
                    lv.y = __float2bfloat16(v1 - __bfloat162float(hv.y));
                    *(__nv_bfloat162*)&g_qh[idx] = hv;
                    *(__nv_bfloat162*)&g_ql[idx] = lv;
                }
            } else {
#pragma unroll
                for (int ni = 0; ni < 8; ni++) {
                    const int n = n0 + wn * 64 + ni * 8 + cc * 2;
                    out[(size_t)m * 1024 + n]     = acc[mi][ni][rr * 2]     + bias[n];
                    out[(size_t)m * 1024 + n + 1] = acc[mi][ni][rr * 2 + 1] + bias[n + 1];
                }
            }
        }
    }
}

// ---------------------------------------------------------------------------
// Attention Pass A: raw scores -> wout (computed tiles only), stats -> g_m/linv
// CTA = (b, h, 128 q rows). Causal: tiles nt > blockIdx.x are fully masked
// (weight == 0.0f exactly) and skipped.
// ---------------------------------------------------------------------------
#define QS 36

__global__ __launch_bounds__(256) void attn_score_kernel(
    const unsigned int* __restrict__ kpm, float* __restrict__ wout)
{
    extern __shared__ unsigned sm[];
    unsigned* sQh = sm;
    unsigned* sQl = sQh + 128 * QS;
    unsigned* sKh = sQl + 128 * QS;
    unsigned* sKl = sKh + 128 * QS;
    unsigned* sKp = sKl + 128 * QS;

    const int b = blockIdx.z, h = blockIdx.y, q0 = blockIdx.x * 128;
    const int tid = threadIdx.x, lane = tid & 31, w = tid >> 5;
    const int r = lane >> 2, cc = lane & 3;

    const unsigned* qhw = (const unsigned*)g_qh;
    const unsigned* qlw = (const unsigned*)g_ql;
    const size_t qbase = ((size_t)(b * HH + h) * SS + q0) * 32;
    const size_t kbase = (size_t)PER / 2 + ((size_t)(b * HH + h) * SS) * 32;

    for (int i = tid; i < 1024; i += 256) {
        const int row = i >> 3, off = (i & 7) * 4;
        *(uint4*)&sQh[row * QS + off] = *(const uint4*)(qhw + qbase + row * 32 + off);
        *(uint4*)&sQl[row * QS + off] = *(const uint4*)(qlw + qbase + row * 32 + off);
    }
    __syncthreads();

    const int qr = w * 16 + r;
    unsigned aQh[4][4], aQl[4][4];
#pragma unroll
    for (int ks = 0; ks < 4; ks++) {
        const int bw = ks * 8 + cc;
        aQh[ks][0] = sQh[qr * QS + bw];
        aQh[ks][1] = sQh[(qr + 8) * QS + bw];
        aQh[ks][2] = sQh[qr * QS + bw + 4];
        aQh[ks][3] = sQh[(qr + 8) * QS + bw + 4];
        aQl[ks][0] = sQl[qr * QS + bw];
        aQl[ks][1] = sQl[(qr + 8) * QS + bw];
        aQl[ks][2] = sQl[qr * QS + bw + 4];
        aQl[ks][3] = sQl[(qr + 8) * QS + bw + 4];
    }

    const int row0 = q0 + qr, row1 = row0 + 8;
    float* wrow0 = wout + ((size_t)(b * HH + h) * SS + row0) * SS;
    float* wrow1 = wout + ((size_t)(b * HH + h) * SS + row1) * SS;

    float m_run[2] = {-1e30f, -1e30f};
    float l_run[2] = {0.0f, 0.0f};

    const int ntmax = blockIdx.x;   // inclusive; tiles beyond are fully masked
    for (int nt = 0; nt <= ntmax; nt++) {
        __syncthreads();
        for (int i = tid; i < 1024; i += 256) {
            const int row = i >> 3, off = (i & 7) * 4;
            const size_t gsrc = kbase + (size_t)(nt * 128 + row) * 32 + off;
            *(uint4*)&sKh[row * QS + off] = *(const uint4*)(qhw + gsrc);
            *(uint4*)&sKl[row * QS + off] = *(const uint4*)(qlw + gsrc);
        }
        if (tid < 128) sKp[tid] = kpm[b * 1024 + nt * 128 + tid];
        __syncthreads();

        float acc[16][4];
#pragma unroll
        for (int ni = 0; ni < 16; ni++)
#pragma unroll
            for (int c = 0; c < 4; c++) acc[ni][c] = 0.0f;

#pragma unroll
        for (int ks = 0; ks < 4; ks++) {
            const int bw = ks * 8 + cc;
#pragma unroll
            for (int ni = 0; ni < 16; ni++) {
                const int krow = ni * 8 + r;
                const unsigned bh0 = sKh[krow * QS + bw];
                const unsigned bh1 = sKh[krow * QS + bw + 4];
                const unsigned bl0 = sKl[krow * QS + bw];
                const unsigned bl1 = sKl[krow * QS + bw + 4];
                mma_bf16(acc[ni], aQh[ks], bh0, bh1);
                mma_bf16(acc[ni], aQh[ks], bl0, bl1);
                mma_bf16(acc[ni], aQl[ks], bh0, bh1);
            }
        }

#pragma unroll
        for (int ni = 0; ni < 16; ni++) {
            const int colb = ni * 8 + cc * 2;
            const int col = nt * 128 + colb;
#pragma unroll
            for (int e = 0; e < 2; e++) {
                const bool pad = (sKp[colb + e] != 0u);
                float s0 = acc[ni][e] * 0.125f;
                if (col + e > row0) s0 += NEGV;
                if (pad) s0 = NEGV;
                acc[ni][e] = s0;
                float s1 = acc[ni][2 + e] * 0.125f;
                if (col + e > row1) s1 += NEGV;
                if (pad) s1 = NEGV;
                acc[ni][2 + e] = s1;
            }
            *(float2*)(wrow0 + col) = make_float2(acc[ni][0], acc[ni][1]);
            *(float2*)(wrow1 + col) = make_float2(acc[ni][2], acc[ni][3]);
        }

        float tm0 = -1e30f, tm1 = -1e30f;
#pragma unroll
        for (int ni = 0; ni < 16; ni++) {
            tm0 = fmaxf(tm0, fmaxf(acc[ni][0], acc[ni][1]));
            tm1 = fmaxf(tm1, fmaxf(acc[ni][2], acc[ni][3]));
        }
        tm0 = fmaxf(tm0, __shfl_xor_sync(0xFFFFFFFFu, tm0, 1));
        tm0 = fmaxf(tm0, __shfl_xor_sync(0xFFFFFFFFu, tm0, 2));
        tm1 = fmaxf(tm1, __shfl_xor_sync(0xFFFFFFFFu, tm1, 1));
        tm1 = fmaxf(tm1, __shfl_xor_sync(0xFFFFFFFFu, tm1, 2));
        const float nm0 = fmaxf(m_run[0], tm0);
        const float nm1 = fmaxf(m_run[1], tm1);
        float s0 = 0.0f, s1 = 0.0f;
#pragma unroll
        for (int ni = 0; ni < 16; ni++) {
            s0 += __expf(acc[ni][0] - nm0) + __expf(acc[ni][1] - nm0);
            s1 += __expf(acc[ni][2] - nm1) + __expf(acc[ni][3] - nm1);
        }
        s0 += __shfl_xor_sync(0xFFFFFFFFu, s0, 1);
        s0 += __shfl_xor_sync(0xFFFFFFFFu, s0, 2);
        s1 += __shfl_xor_sync(0xFFFFFFFFu, s1, 1);
        s1 += __shfl_xor_sync(0xFFFFFFFFu, s1, 2);
        l_run[0] = l_run[0] * __expf(m_run[0] - nm0) + s0;
        l_run[1] = l_run[1] * __expf(m_run[1] - nm1) + s1;
        m_run[0] = nm0; m_run[1] = nm1;
    }

    if (cc == 0) {
        const int sbase_ = (b * HH + h) * SS;
        g_m[sbase_ + row0] = m_run[0];
        g_m[sbase_ + row1] = m_run[1];
        g_linv[sbase_ + row0] = 1.0f / l_run[0];
        g_linv[sbase_ + row1] = 1.0f / l_run[1];
    }
}

// ---------------------------------------------------------------------------
// Attention Pass B: w = exp(s-m)/l (write back), ctx = W @ V (hi/lo bf16 out).
// Fully-masked tiles (kt > blockIdx.x): write zero weights, skip compute.
// ---------------------------------------------------------------------------
#define WS 68

__global__ __launch_bounds__(256) void attn_av_kernel(float* __restrict__ wout)
{
    extern __shared__ unsigned sm[];
    unsigned* sWh = sm;
    unsigned* sWl = sWh + 128 * WS;
    unsigned* sVh = sWl + 128 * WS;
    unsigned* sVl = sVh + 64 * WS;
    float*    sM  = (float*)(sVl + 64 * WS);
    float*    sLi = sM + 128;

    const int b = blockIdx.z, h = blockIdx.y, q0 = blockIdx.x * 128;
    const int tid = threadIdx.x, lane = tid & 31, w = tid >> 5;
    const int r = lane >> 2, cc = lane & 3;

    const unsigned* vhw = (const unsigned*)g_qh + (size_t)PER
                        + ((size_t)(b * HH + h) * SS) * 32;
    const unsigned* vlw = (const unsigned*)g_ql + (size_t)PER
                        + ((size_t)(b * HH + h) * SS) * 32;
    float* wbase = wout + ((size_t)(b * HH + h) * SS + q0) * SS;

    if (tid < 128) {
        const int sb_ = (b * HH + h) * SS + q0;
        sM[tid]  = g_m[sb_ + tid];
        sLi[tid] = g_linv[sb_ + tid];
    }
    __syncthreads();

    float acc[8][4];
#pragma unroll
    for (int ni = 0; ni < 8; ni++)
#pragma unroll
        for (int c = 0; c < 4; c++) acc[ni][c] = 0.0f;

    const int qr = w * 16 + r;
    const int ktmax = blockIdx.x;

    for (int kt = 0; kt <= ktmax; kt++) {
        if (kt > 0) __syncthreads();
        // scores -> weights (write back) + bf16 hi/lo smem
        for (int i = tid; i < 4096; i += 256) {
            const int row = i >> 5, c4 = (i & 31) * 4;
            float* p = wbase + (size_t)row * SS + kt * 128 + c4;
            float4 s = *(const float4*)p;
            const float mm = sM[row], li = sLi[row];
            float4 wv;
            wv.x = __expf(s.x - mm) * li;
            wv.y = __expf(s.y - mm) * li;
            wv.z = __expf(s.z - mm) * li;
            wv.w = __expf(s.w - mm) * li;
            *(float4*)p = wv;
            float rx, ry;
            unsigned h0 = pack_hi(wv.x, wv.y, rx, ry); unsigned l0 = pack_lo(rx, ry);
            unsigned h1 = pack_hi(wv.z, wv.w, rx, ry); unsigned l1 = pack_lo(rx, ry);
            const int base = row * WS + (c4 >> 1);
            sWh[base] = h0; sWh[base + 1] = h1;
            sWl[base] = l0; sWl[base + 1] = l1;
        }
        // V tile transposed: [d][key], preconverted hi/lo
        {
            __nv_bfloat16* tVh = (__nv_bfloat16*)sVh;
            __nv_bfloat16* tVl = (__nv_bfloat16*)sVl;
            for (int i = tid; i < 4096; i += 256) {
                const int key = i >> 5, dw = i & 31;
                const size_t gsrc = (size_t)(kt * 128 + key) * 32 + dw;
                unsigned wh = vhw[gsrc];
                unsigned wl = vlw[gsrc];
                __nv_bfloat162 h2 = *(__nv_bfloat162*)&wh;
                __nv_bfloat162 l2 = *(__nv_bfloat162*)&wl;
                tVh[(2 * dw) * (2 * WS) + key]     = h2.x;
                tVh[(2 * dw + 1) * (2 * WS) + key] = h2.y;
                tVl[(2 * dw) * (2 * WS) + key]     = l2.x;
                tVl[(2 * dw + 1) * (2 * WS) + key] = l2.y;
            }
        }
        __syncthreads();

#pragma unroll
        for (int ks = 0; ks < 8; ks++) {
            const int bw = ks * 8 + cc;
            unsigned ah[4], al[4];
            ah[0] = sWh[qr * WS + bw];
            ah[1] = sWh[(qr + 8) * WS + bw];
            ah[2] = sWh[qr * WS + bw + 4];
            ah[3] = sWh[(qr + 8) * WS + bw + 4];
            al[0] = sWl[qr * WS + bw];
            al[1] = sWl[(qr + 8) * WS + bw];
            al[2] = sWl[qr * WS + bw + 4];
            al[3] = sWl[(qr + 8) * WS + bw + 4];
#pragma unroll
            for (int ni = 0; ni < 8; ni++) {
                const int vrow = ni * 8 + r;
                const unsigned bh0 = sVh[vrow * WS + bw];
                const unsigned bh1 = sVh[vrow * WS + bw + 4];
                const unsigned bl0 = sVl[vrow * WS + bw];
                const unsigned bl1 = sVl[vrow * WS + bw + 4];
                mma_bf16(acc[ni], ah, bh0, bh1);
                mma_bf16(acc[ni], ah, bl0, bl1);
                mma_bf16(acc[ni], al, bh0, bh1);
            }
        }
    }

    // zero-fill weights for fully-masked tiles (exact: reference exp == 0.0f)
    {
        const float4 z4 = make_float4(0.f, 0.f, 0.f, 0.f);
        for (int kt = ktmax + 1; kt < 8; kt++)
            for (int i = tid; i < 4096; i += 256) {
                const int row = i >> 5, c4 = (i & 31) * 4;
                *(float4*)(wbase + (size_t)row * SS + kt * 128 + c4) = z4;
            }
    }

    // ctx epilogue: hi/lo bf16 for the out-projection
    __nv_bfloat16* cth = (__nv_bfloat16*)g_cth;
    __nv_bfloat16* ctl = (__nv_bfloat16*)g_ctl;
    const size_t o0 = ((size_t)(b * SS + q0 + qr)) * EE + h * DKK;
    const size_t o1 = ((size_t)(b * SS + q0 + qr + 8)) * EE + h * DKK;
#pragma unroll
    for (int ni = 0; ni < 8; ni++) {
        const int d0 = ni * 8 + cc * 2;
        __nv_bfloat162 hv, lv;
        hv.x = __float2bfloat16(acc[ni][0]);
        lv.x = __float2bfloat16(acc[ni][0] - __bfloat162float(hv.x));
        hv.y = __float2bfloat16(acc[ni][1]);
        lv.y = __float2bfloat16(acc[ni][1] - __bfloat162float(hv.y));
        *(__nv_bfloat162*)(cth + o0 + d0) = hv;
        *(__nv_bfloat162*)(ctl + o0 + d0) = lv;
        hv.x = __float2bfloat16(acc[ni][2]);
        lv.x = __float2bfloat16(acc[ni][2] - __bfloat162float(hv.x));
        hv.y = __float2bfloat16(acc[ni][3]);
        lv.y = __float2bfloat16(acc[ni][3] - __bfloat162float(hv.y));
        *(__nv_bfloat162*)(cth + o1 + d0) = hv;
        *(__nv_bfloat162*)(ctl + o1 + d0) = lv;
    }
}

// ---------------------------------------------------------------------------
extern "C" void kernel_launch(void* const* d_in, const int* in_sizes, int n_in,
                              void* d_out, int out_size)
{
    const float*        x     = (const float*)d_in[0];
    const unsigned int* kpm   = (const unsigned int*)d_in[2];
    const float*        qkv_w = (const float*)d_in[3];
    const float*        qkv_b = (const float*)d_in[4];
    const float*        out_w = (const float*)d_in[5];
    const float*        out_b = (const float*)d_in[6];

    float* out  = (float*)d_out;
    float* wout = out + (size_t)BB * SS * EE;

    const int gemmSmem  = 2 * 4 * 2560 * 4;                         // 80 KB
    const int scoreSmem = (4 * 128 * QS + 128) * 4;                 // ~74 KB
    const int avSmem    = (2 * 128 * WS + 2 * 64 * WS + 256) * 4;   // ~105 KB
    cudaFuncSetAttribute(gemm_bf16_kernel<0>,
                         cudaFuncAttributeMaxDynamicSharedMemorySize, gemmSmem);
    cudaFuncSetAttribute(gemm_bf16_kernel<1>,
                         cudaFuncAttributeMaxDynamicSharedMemorySize, gemmSmem);
    cudaFuncSetAttribute(attn_score_kernel,
                         cudaFuncAttributeMaxDynamicSharedMemorySize, scoreSmem);
    cudaFuncSetAttribute(attn_av_kernel,
                         cudaFuncAttributeMaxDynamicSharedMemorySize, avSmem);

    // 0) one-time conversions (per launch)
    cvt_kernel<<<4096, 256>>>(x,     0, 4096 * 256);
    cvt_kernel<<<3072, 256>>>(qkv_w, 1, 3072 * 256);
    cvt_kernel<<<1024, 256>>>(out_w, 2, 1024 * 256);

    // 1) QKV projection -> g_qh/g_ql
    gemm_bf16_kernel<0><<<dim3(24, 32), 256, gemmSmem>>>(qkv_b, kpm, nullptr);

    // 2a) scores + stats
    attn_score_kernel<<<dim3(8, HH, BB), 256, scoreSmem>>>(kpm, wout);

    // 2b) softmax weights + ctx
    attn_av_kernel<<<dim3(8, HH, BB), 256, avSmem>>>(wout);

    // 3) output projection
    gemm_bf16_kernel<1><<<dim3(8, 32), 256, gemmSmem>>>(out_b, nullptr, out);
}